// round 1
// baseline (speedup 1.0000x reference)
#include <cuda_runtime.h>

// DropBlock: x [64,256,64,64] f32, u [58,58] f32.
// BLOCK_SIZE=7, DROP_PROB=0.1
// mask[y,x] = 0 if any drop[i,j] (i in [y-6,y]&[0,57], j likewise), else 1
// scale = 4096 / sum(mask); out = x * (mask*scale) broadcast over N,C.

#define H 64
#define W 64
#define HW 4096
#define US 58           // H - BS + 1
#define BS 7
#define DROP_PROB 0.1f

// per-(h,w) multiplier table, computed by kernel 1, read by kernel 2
__device__ float d_mult[HW];

// ---------------- Kernel 1: build multiplier table ----------------
// Single block, 256 threads.
__global__ void build_mask_kernel(const float* __restrict__ u) {
    __shared__ float s_u[US * US];          // 13.4 KB
    __shared__ float s_mask[HW];            // 16 KB
    __shared__ float s_red[256];

    int tid = threadIdx.x;

    // load u into shared
    for (int i = tid; i < US * US; i += 256)
        s_u[i] = u[i];
    __syncthreads();

    // compute mask per pixel
    for (int p = tid; p < HW; p += 256) {
        int y = p >> 6;
        int x = p & 63;
        int i0 = y - (BS - 1); if (i0 < 0) i0 = 0;
        int i1 = y;            if (i1 > US - 1) i1 = US - 1;
        int j0 = x - (BS - 1); if (j0 < 0) j0 = 0;
        int j1 = x;            if (j1 > US - 1) j1 = US - 1;
        float keep = 1.0f;
        for (int i = i0; i <= i1; i++) {
            for (int j = j0; j <= j1; j++) {
                if (s_u[i * US + j] < DROP_PROB) keep = 0.0f;
            }
        }
        s_mask[p] = keep;
    }
    __syncthreads();

    // reduce sum of mask
    float acc = 0.0f;
    for (int p = tid; p < HW; p += 256)
        acc += s_mask[p];
    s_red[tid] = acc;
    __syncthreads();
    for (int s = 128; s > 0; s >>= 1) {
        if (tid < s) s_red[tid] += s_red[tid + s];
        __syncthreads();
    }
    __shared__ float s_scale;
    if (tid == 0) {
        float sum = s_red[0];
        s_scale = (float)HW / sum;   // matches jnp: numel / mask.sum()
    }
    __syncthreads();
    float scale = s_scale;

    for (int p = tid; p < HW; p += 256)
        d_mult[p] = s_mask[p] * scale;
}

// ---------------- Kernel 2: streaming multiply ----------------
// One float4 per thread; hw multiplier table is 16KB, hot in L1/L2.
__global__ void apply_mask_kernel(const float4* __restrict__ x4,
                                  float4* __restrict__ out4,
                                  int n4) {
    int idx = blockIdx.x * blockDim.x + threadIdx.x;
    if (idx >= n4) return;
    // element base = idx*4; hw = (idx*4) & 4095 -> float4-index into mult: idx & 1023
    const float4* m4 = reinterpret_cast<const float4*>(d_mult);
    float4 m = __ldg(&m4[idx & 1023]);
    float4 v = x4[idx];
    v.x *= m.x; v.y *= m.y; v.z *= m.z; v.w *= m.w;
    out4[idx] = v;
}

extern "C" void kernel_launch(void* const* d_in, const int* in_sizes, int n_in,
                              void* d_out, int out_size) {
    const float* x = (const float*)d_in[0];
    const float* u = (const float*)d_in[1];
    float* out = (float*)d_out;

    build_mask_kernel<<<1, 256>>>(u);

    int n4 = out_size / 4;               // 16,777,216 float4s
    int threads = 256;
    int blocks = (n4 + threads - 1) / threads;
    apply_mask_kernel<<<blocks, threads>>>(
        (const float4*)x, (float4*)out, n4);
}

// round 2
// speedup vs baseline: 1.2118x; 1.2118x over previous
#include <cuda_runtime.h>

// DropBlock: x [64,256,64,64] f32, u [58,58] f32.
// BLOCK_SIZE=7, DROP_PROB=0.1
// mask[y,x] = 0 if any drop[i,j] with i in [y-6,y]&[0,57], j in [x-6,x]&[0,57]
// scale = 4096 / sum(mask); out = x * (mask*scale) broadcast over N,C.

#define H 64
#define W 64
#define HW 4096
#define US 58           // H - BS + 1
#define BS 7
#define DROP_PROB 0.1f

// per-(h,w) multiplier table, computed by kernel 1, read by kernel 2
__device__ __align__(16) float d_mult[HW];

// ---------------- Kernel 1: build multiplier table (bitboards) ----------------
// Single block, 1024 threads. Each mask row is a 64-bit word.
__global__ void build_mask_kernel(const float* __restrict__ u) {
    __shared__ unsigned long long s_drop[US];   // per-row drop bits (bit j = block at (i,j) dropped)
    __shared__ unsigned long long s_hdil[US];   // horizontally dilated rows
    __shared__ unsigned long long s_vdil[H];    // fully dilated rows (bit x = pixel dropped)
    __shared__ int s_sum;
    __shared__ float s_scale;

    int tid = threadIdx.x;

    if (tid < US) s_drop[tid] = 0ULL;
    if (tid == 0) s_sum = 0;
    __syncthreads();

    // build drop bitmasks: 3364 elements over 1024 threads
    for (int p = tid; p < US * US; p += 1024) {
        int i = p / US;
        int j = p - i * US;
        if (u[p] < DROP_PROB)
            atomicOr(&s_drop[i], 1ULL << j);
    }
    __syncthreads();

    // horizontal dilation: bit x set if any drop bit j in [x-6, x]
    if (tid < US) {
        unsigned long long b = s_drop[tid];
        unsigned long long h = b;
        #pragma unroll
        for (int s = 1; s < BS; s++) h |= b << s;   // j up to 57 -> x up to 63, no overflow
        s_hdil[tid] = h;
    }
    __syncthreads();

    // vertical dilation + popcount sum
    if (tid < H) {
        int y = tid;
        int i0 = y - (BS - 1); if (i0 < 0) i0 = 0;
        int i1 = y;            if (i1 > US - 1) i1 = US - 1;
        unsigned long long v = 0ULL;
        for (int i = i0; i <= i1; i++) v |= s_hdil[i];
        s_vdil[y] = v;
        int keep = W - __popcll(v);
        // reduce within the two warps holding tid<64
        #pragma unroll
        for (int off = 16; off > 0; off >>= 1)
            keep += __shfl_down_sync(0xFFFFFFFFu, keep, off);
        if ((tid & 31) == 0) atomicAdd(&s_sum, keep);
    }
    __syncthreads();

    if (tid == 0) s_scale = (float)HW / (float)s_sum;
    __syncthreads();
    float scale = s_scale;

    // write multiplier table: 4096 over 1024 threads
    for (int p = tid; p < HW; p += 1024) {
        int y = p >> 6;
        int x = p & 63;
        float m = ((s_vdil[y] >> x) & 1ULL) ? 0.0f : scale;
        d_mult[p] = m;
    }
}

// ---------------- Kernel 2: streaming multiply ----------------
// Two float4 per thread, front-batched loads; streaming cache hints
// (x and out have zero reuse; the 16KB mult table stays hot via __ldg).
__global__ void apply_mask_kernel(const float4* __restrict__ x4,
                                  float4* __restrict__ out4,
                                  int n4) {
    int t = blockIdx.x * blockDim.x + threadIdx.x;
    int i0 = t * 2;
    int i1 = i0 + 1;
    if (i1 >= n4) {
        if (i0 < n4) {
            const float4* m4 = reinterpret_cast<const float4*>(d_mult);
            float4 m = __ldg(&m4[i0 & 1023]);
            float4 v = __ldcs(&x4[i0]);
            v.x *= m.x; v.y *= m.y; v.z *= m.z; v.w *= m.w;
            __stcs(&out4[i0], v);
        }
        return;
    }
    const float4* m4 = reinterpret_cast<const float4*>(d_mult);
    // front-batch both global loads for MLP
    float4 v0 = __ldcs(&x4[i0]);
    float4 v1 = __ldcs(&x4[i1]);
    float4 m0 = __ldg(&m4[i0 & 1023]);
    float4 m1 = __ldg(&m4[i1 & 1023]);
    v0.x *= m0.x; v0.y *= m0.y; v0.z *= m0.z; v0.w *= m0.w;
    v1.x *= m1.x; v1.y *= m1.y; v1.z *= m1.z; v1.w *= m1.w;
    __stcs(&out4[i0], v0);
    __stcs(&out4[i1], v1);
}

extern "C" void kernel_launch(void* const* d_in, const int* in_sizes, int n_in,
                              void* d_out, int out_size) {
    const float* x = (const float*)d_in[0];
    const float* u = (const float*)d_in[1];
    float* out = (float*)d_out;

    build_mask_kernel<<<1, 1024>>>(u);

    int n4 = out_size / 4;                       // 16,777,216 float4s
    int pairs = (n4 + 1) / 2;                    // 2 float4 per thread
    int threads = 256;
    int blocks = (pairs + threads - 1) / threads;
    apply_mask_kernel<<<blocks, threads>>>(
        (const float4*)x, (float4*)out, n4);
}